// round 10
// baseline (speedup 1.0000x reference)
#include <cuda_runtime.h>
#include <cuda_fp16.h>
#include <cstdint>
#include <math.h>

#define N 8192
#define D 1024
#define BM 128
#define BN 128
#define BK 64
#define STAGES 3
#define THREADS 128
#define COLSPLITS 8
#define TILES 8                   // j-tiles per CTA (8192 / BN / COLSPLITS)
#define KCHUNKS (D / BK)          // 16
#define TOTCH (TILES * KCHUNKS)   // 128
#define NPART 16                  // colsplit(8) x wn(2)

#define STAGE_BYTES 32768         // A 16KB + B 16KB, SW128 layout
#define SMEM_TOTAL (STAGES * STAGE_BYTES)   // 98304

// device scratch
__device__ __half g_Rh[(long)N * D];
__device__ __half g_Lh[(long)N * D];
__device__ float g_pm[NPART * N];
__device__ float g_ps[NPART * N];
__device__ float g_diag[N];

// ---------------------------------------------------------------------------
// helpers
// ---------------------------------------------------------------------------
__device__ __forceinline__ uint32_t smem_u32(const void* p) {
    uint32_t a;
    asm("{ .reg .u64 t; cvta.to.shared.u64 t, %1; cvt.u32.u64 %0, t; }" : "=r"(a) : "l"(p));
    return a;
}
__device__ __forceinline__ void cp16(uint32_t saddr, const void* g) {
    asm volatile("cp.async.cg.shared.global [%0],[%1],16;\n" :: "r"(saddr), "l"(g));
}
__device__ __forceinline__ void ldsm4(uint32_t* r, uint32_t addr) {
    asm volatile("ldmatrix.sync.aligned.m8n8.x4.shared.b16 {%0,%1,%2,%3}, [%4];"
                 : "=r"(r[0]), "=r"(r[1]), "=r"(r[2]), "=r"(r[3]) : "r"(addr));
}
// fp16 accumulate MMA
__device__ __forceinline__ void mma16816h(uint32_t* c, const uint32_t* a, uint32_t b0, uint32_t b1) {
    asm volatile(
        "mma.sync.aligned.m16n8k16.row.col.f16.f16.f16.f16 "
        "{%0,%1},{%2,%3,%4,%5},{%6,%7},{%0,%1};"
        : "+r"(c[0]), "+r"(c[1])
        : "r"(a[0]), "r"(a[1]), "r"(a[2]), "r"(a[3]), "r"(b0), "r"(b1));
}
__device__ __forceinline__ float ex2f(float x) {
    float r;
    asm("ex2.approx.ftz.f32 %0, %1;" : "=f"(r) : "f"(x));
    return r;
}

// ---------------------------------------------------------------------------
// Kernel 1: fp32 -> fp16 conversion, fused with exact fp32 diagonal dot.
// One block == one row (256 threads x 4 elems = 1024 = D).
// ---------------------------------------------------------------------------
__global__ void convert_kernel(const float* __restrict__ R, const float* __restrict__ L) {
    __shared__ float wsum[8];
    const int row = blockIdx.x, tid = threadIdx.x;
    const long i = (long)row * D + tid * 4;
    float4 r = *(const float4*)(R + i);
    float4 l = *(const float4*)(L + i);
    *(__half2*)(g_Rh + i)     = __floats2half2_rn(r.x, r.y);
    *(__half2*)(g_Rh + i + 2) = __floats2half2_rn(r.z, r.w);
    *(__half2*)(g_Lh + i)     = __floats2half2_rn(l.x, l.y);
    *(__half2*)(g_Lh + i + 2) = __floats2half2_rn(l.z, l.w);
    float s = r.x * l.x + r.y * l.y + r.z * l.z + r.w * l.w;
    #pragma unroll
    for (int o = 16; o > 0; o >>= 1) s += __shfl_xor_sync(0xffffffffu, s, o);
    if ((tid & 31) == 0) wsum[tid >> 5] = s;
    __syncthreads();
    if (tid < 8) {
        float t = wsum[tid];
        t += __shfl_xor_sync(0xffu, t, 1);
        t += __shfl_xor_sync(0xffu, t, 2);
        t += __shfl_xor_sync(0xffu, t, 4);
        if (tid == 0) g_diag[row] = t;
    }
}

// dummy launches: keep lse_kernel at ncu -s 5 capture position
__global__ void pad_kernel() {}

// ---------------------------------------------------------------------------
// Kernel 3: mma.sync fp16-accum GEMM, 128 threads/CTA, 2 CTAs/SM
// ---------------------------------------------------------------------------
__global__ void __launch_bounds__(THREADS, 2) lse_kernel() {
    extern __shared__ char smem[];
    const uint32_t sb = smem_u32(smem);
    const int tid = threadIdx.x, wid = tid >> 5, lane = tid & 31;
    const int wm = wid >> 1, wn = wid & 1;       // 2x2 warp grid, 64x64 per warp
    const int rowBase = (int)(blockIdx.x >> 3) * BM;
    const int csplit = blockIdx.x & 7;
    const long colBase0 = (long)csplit * (TILES * BN);
    const float LOG2E = 1.4426950408889634f;

    // ---- precomputed cp.async geometry (A and B tiles share shape 128x64) ----
    uint32_t swoff[8];
    long goff[8];
    #pragma unroll
    for (int i = 0; i < 8; i++) {
        int idx = i * THREADS + tid;              // 0..1023 16B-lines
        int row = idx >> 3, cc = idx & 7;
        uint32_t off = row * 128 + cc * 16;
        swoff[i] = off ^ ((off >> 3) & 0x70);
        goff[i] = (long)row * D + cc * 8;
    }
    const __half* Abase = g_Rh + (long)rowBase * D;
    const __half* Bbase = g_Lh + colBase0 * D;

    // ---- ldmatrix geometry ----
    const int q = lane >> 3, j = lane & 7;
    uint32_t aoff[4], asw[4];
    #pragma unroll
    for (int mi = 0; mi < 4; mi++) {
        int row = wm * 64 + mi * 16 + (q & 1) * 8 + j;
        aoff[mi] = row * 128;
        asw[mi] = (row & 7) << 4;
    }
    const uint32_t axk = (q >> 1) * 16;
    uint32_t boff[4], bsw[4];
    #pragma unroll
    for (int np = 0; np < 4; np++) {
        int row = wn * 64 + np * 16 + (q >> 1) * 8 + j;
        boff[np] = row * 128;
        bsw[np] = (row & 7) << 4;
    }
    const uint32_t bxk = (q & 1) * 16;

    uint32_t c[4][8][2];
    #pragma unroll
    for (int mi = 0; mi < 4; mi++)
        #pragma unroll
        for (int ni = 0; ni < 8; ni++) { c[mi][ni][0] = 0u; c[mi][ni][1] = 0u; }

    float st_m[4][2], st_s[4][2];
    #pragma unroll
    for (int mi = 0; mi < 4; mi++)
        #pragma unroll
        for (int h = 0; h < 2; h++) { st_m[mi][h] = -INFINITY; st_s[mi][h] = 0.f; }

    // chunk load: g -> (t = g>>4, kc = g&15), stage = g%3
    auto issue_load = [&](int g) {
        const int t = g >> 4, kc = g & 15, st = g % 3;
        const __half* Asrc = Abase + kc * BK;
        const __half* Bsrc = Bbase + (long)t * BN * D + kc * BK;
        const uint32_t Ab = sb + st * STAGE_BYTES;
        const uint32_t Bb = Ab + 16384;
        #pragma unroll
        for (int i = 0; i < 8; i++) cp16(Ab + swoff[i], Asrc + goff[i]);
        #pragma unroll
        for (int i = 0; i < 8; i++) cp16(Bb + swoff[i], Bsrc + goff[i]);
        asm volatile("cp.async.commit_group;");
    };

    // prologue: chunks 0,1 in flight
    issue_load(0);
    issue_load(1);

    for (int g = 0; g < TOTCH; ++g) {
        asm volatile("cp.async.wait_group 1;");
        __syncthreads();
        if (g + 2 < TOTCH) issue_load(g + 2);

        const int st = g % 3;
        const uint32_t Ast = sb + st * STAGE_BYTES;
        const uint32_t Bst = Ast + 16384;
        #pragma unroll
        for (int kk = 0; kk < 4; ++kk) {
            const uint32_t kx = kk * 32;
            uint32_t a[4][4], b[4][4];
            #pragma unroll
            for (int mi = 0; mi < 4; mi++)
                ldsm4(a[mi], Ast + aoff[mi] + ((kx + axk) ^ asw[mi]));
            #pragma unroll
            for (int np = 0; np < 4; np++)
                ldsm4(b[np], Bst + boff[np] + ((kx + bxk) ^ bsw[np]));
            #pragma unroll
            for (int mi = 0; mi < 4; mi++)
                #pragma unroll
                for (int ni = 0; ni < 8; ni++) {
                    const int np = ni >> 1, lo = ni & 1;
                    mma16816h(c[mi][ni], a[mi], b[np][lo * 2], b[np][lo * 2 + 1]);
                }
        }

        if ((g & 15) == 15) {
            // ---- per-j-tile online LSE update, register-resident ----
            #pragma unroll
            for (int mi = 0; mi < 4; mi++)
                #pragma unroll
                for (int h = 0; h < 2; h++) {
                    float2 v[8];
                    #pragma unroll
                    for (int ni = 0; ni < 8; ni++)
                        v[ni] = __half22float2(*(__half2*)&c[mi][ni][h]);
                    float mx = fmaxf(v[0].x, v[0].y);
                    #pragma unroll
                    for (int ni = 1; ni < 8; ni++)
                        mx = fmaxf(mx, fmaxf(v[ni].x, v[ni].y));
                    mx = fmaxf(mx, __shfl_xor_sync(0xffffffffu, mx, 1));
                    mx = fmaxf(mx, __shfl_xor_sync(0xffffffffu, mx, 2));
                    const float nm = fmaxf(st_m[mi][h], mx);
                    const float nb = -nm * LOG2E;
                    float s0 = 0.f, s1 = 0.f;
                    #pragma unroll
                    for (int ni = 0; ni < 8; ni++) {
                        s0 += ex2f(fmaf(v[ni].x, LOG2E, nb));
                        s1 += ex2f(fmaf(v[ni].y, LOG2E, nb));
                    }
                    float sum = s0 + s1;
                    sum += __shfl_xor_sync(0xffffffffu, sum, 1);
                    sum += __shfl_xor_sync(0xffffffffu, sum, 2);
                    st_s[mi][h] = st_s[mi][h] * ex2f(fmaf(st_m[mi][h], LOG2E, nb)) + sum;
                    st_m[mi][h] = nm;
                }
            #pragma unroll
            for (int mi = 0; mi < 4; mi++)
                #pragma unroll
                for (int ni = 0; ni < 8; ni++) { c[mi][ni][0] = 0u; c[mi][ni][1] = 0u; }
        }
    }

    // final per-row partial write
    if ((lane & 3) == 0) {
        const int part = csplit * 2 + wn;
        #pragma unroll
        for (int mi = 0; mi < 4; mi++)
            #pragma unroll
            for (int h = 0; h < 2; h++) {
                int row = rowBase + wm * 64 + mi * 16 + h * 8 + (lane >> 2);
                g_pm[part * N + row] = st_m[mi][h];
                g_ps[part * N + row] = st_s[mi][h];
            }
    }
}

// ---------------------------------------------------------------------------
// Kernel 4: merge 16 partials per row, reduce to the scalar (float math)
// ---------------------------------------------------------------------------
__global__ void finalize_kernel(float* __restrict__ out) {
    __shared__ double red[256];
    double acc = 0.0;
    for (int i = threadIdx.x; i < N; i += 256) {
        float mm = -INFINITY;
        #pragma unroll
        for (int p = 0; p < NPART; p++) mm = fmaxf(mm, g_pm[p * N + i]);
        float ss = 0.f;
        #pragma unroll
        for (int p = 0; p < NPART; p++)
            ss += g_ps[p * N + i] * __expf(g_pm[p * N + i] - mm);
        float lse = mm + logf(ss);
        acc += (double)lse - (double)g_diag[i];
    }
    red[threadIdx.x] = acc;
    __syncthreads();
    for (int s = 128; s > 0; s >>= 1) {
        if (threadIdx.x < s) red[threadIdx.x] += red[threadIdx.x + s];
        __syncthreads();
    }
    if (threadIdx.x == 0) out[0] = (float)(red[0] / (double)N);
}

// ---------------------------------------------------------------------------
extern "C" void kernel_launch(void* const* d_in, const int* in_sizes, int n_in,
                              void* d_out, int out_size) {
    const float* R = (const float*)d_in[0];   // rpr_r [N, D]
    const float* L = (const float*)d_in[1];   // rpr_l [N, D]
    float* out = (float*)d_out;

    cudaFuncSetAttribute(lse_kernel, cudaFuncAttributeMaxDynamicSharedMemorySize, SMEM_TOTAL);

    convert_kernel<<<N, 256>>>(R, L);
    pad_kernel<<<1, 32>>>();
    pad_kernel<<<1, 32>>>();
    lse_kernel<<<(N / BM) * COLSPLITS, THREADS, SMEM_TOTAL>>>();
    finalize_kernel<<<1, 256>>>(out);
}

// round 11
// speedup vs baseline: 1.1524x; 1.1524x over previous
#include <cuda_runtime.h>
#include <cuda_fp16.h>
#include <cstdint>
#include <math.h>

#define N 8192
#define D 1024
#define BM 128
#define BN 128
#define BK 64
#define THREADS 128
#define NCTAS 296                 // 148 SMs x 2 resident CTAs
#define NJOBS 4096                // 64 row-blocks x 64 j-tiles
#define STAGE_BYTES 32768         // A 16KB + B 16KB, SW128 layout
#define SMEM_TOTAL (3 * STAGE_BYTES)   // 98304

// device scratch
__device__ __half g_Rh[(long)N * D];
__device__ __half g_Lh[(long)N * D];
__device__ float g_pm[NJOBS * 256];   // per (job, wn, row-in-block) partial max
__device__ float g_ps[NJOBS * 256];   // per (job, wn, row-in-block) partial sum
__device__ float g_diag[N];
__device__ float g_row[N];

// ---------------------------------------------------------------------------
// helpers
// ---------------------------------------------------------------------------
__device__ __forceinline__ uint32_t smem_u32(const void* p) {
    uint32_t a;
    asm("{ .reg .u64 t; cvta.to.shared.u64 t, %1; cvt.u32.u64 %0, t; }" : "=r"(a) : "l"(p));
    return a;
}
__device__ __forceinline__ void cp16(uint32_t saddr, const void* g) {
    asm volatile("cp.async.cg.shared.global [%0],[%1],16;\n" :: "r"(saddr), "l"(g));
}
__device__ __forceinline__ void ldsm4(uint32_t* r, uint32_t addr) {
    asm volatile("ldmatrix.sync.aligned.m8n8.x4.shared.b16 {%0,%1,%2,%3}, [%4];"
                 : "=r"(r[0]), "=r"(r[1]), "=r"(r[2]), "=r"(r[3]) : "r"(addr));
}
// fp16 accumulate MMA
__device__ __forceinline__ void mma16816h(uint32_t* c, const uint32_t* a, uint32_t b0, uint32_t b1) {
    asm volatile(
        "mma.sync.aligned.m16n8k16.row.col.f16.f16.f16.f16 "
        "{%0,%1},{%2,%3,%4,%5},{%6,%7},{%0,%1};"
        : "+r"(c[0]), "+r"(c[1])
        : "r"(a[0]), "r"(a[1]), "r"(a[2]), "r"(a[3]), "r"(b0), "r"(b1));
}
__device__ __forceinline__ float ex2f(float x) {
    float r;
    asm("ex2.approx.ftz.f32 %0, %1;" : "=f"(r) : "f"(x));
    return r;
}

// ---------------------------------------------------------------------------
// Kernel 1: fp32 -> fp16 conversion, fused with exact fp32 diagonal dot.
// One block == one row (256 threads x 4 elems = 1024 = D).
// ---------------------------------------------------------------------------
__global__ void convert_kernel(const float* __restrict__ R, const float* __restrict__ L) {
    __shared__ float wsum[8];
    const int row = blockIdx.x, tid = threadIdx.x;
    const long i = (long)row * D + tid * 4;
    float4 r = *(const float4*)(R + i);
    float4 l = *(const float4*)(L + i);
    *(__half2*)(g_Rh + i)     = __floats2half2_rn(r.x, r.y);
    *(__half2*)(g_Rh + i + 2) = __floats2half2_rn(r.z, r.w);
    *(__half2*)(g_Lh + i)     = __floats2half2_rn(l.x, l.y);
    *(__half2*)(g_Lh + i + 2) = __floats2half2_rn(l.z, l.w);
    float s = r.x * l.x + r.y * l.y + r.z * l.z + r.w * l.w;
    #pragma unroll
    for (int o = 16; o > 0; o >>= 1) s += __shfl_xor_sync(0xffffffffu, s, o);
    if ((tid & 31) == 0) wsum[tid >> 5] = s;
    __syncthreads();
    if (tid < 8) {
        float t = wsum[tid];
        t += __shfl_xor_sync(0xffu, t, 1);
        t += __shfl_xor_sync(0xffu, t, 2);
        t += __shfl_xor_sync(0xffu, t, 4);
        if (tid == 0) g_diag[row] = t;
    }
}

// dummy launches: keep lse_kernel at ncu -s 5 capture position
__global__ void pad_kernel() {}

// ---------------------------------------------------------------------------
// Kernel 3: mma.sync fp16-accum GEMM, flat job scheduler (grid = 296)
// job gj in [0, 4096): rb = gj>>6 (row block), jt = gj&63 (column tile).
// CTA k runs jobs k, k+296, k+592, ...  Each job = 16 K-chunks + epilogue.
// ---------------------------------------------------------------------------
__global__ void __launch_bounds__(THREADS, 2) lse_kernel() {
    extern __shared__ char smem[];
    const uint32_t sb = smem_u32(smem);
    const int tid = threadIdx.x, wid = tid >> 5, lane = tid & 31;
    const int wm = wid >> 1, wn = wid & 1;       // 2x2 warp grid, 64x64 per warp
    const int cta = blockIdx.x;
    const int njobs = (NJOBS - cta + NCTAS - 1) / NCTAS;   // 13 or 14
    const int totc = njobs * 16;
    const float LOG2E = 1.4426950408889634f;

    // ---- precomputed cp.async geometry (A and B tiles share shape 128x64) ----
    uint32_t swoff[8];
    long goff[8];
    #pragma unroll
    for (int i = 0; i < 8; i++) {
        int idx = i * THREADS + tid;              // 0..1023 16B-lines
        int row = idx >> 3, cc = idx & 7;
        uint32_t off = row * 128 + cc * 16;
        swoff[i] = off ^ ((off >> 3) & 0x70);
        goff[i] = (long)row * D + cc * 8;
    }

    // ---- ldmatrix geometry ----
    const int q = lane >> 3, j = lane & 7;
    uint32_t aoff[4], asw[4];
    #pragma unroll
    for (int mi = 0; mi < 4; mi++) {
        int row = wm * 64 + mi * 16 + (q & 1) * 8 + j;
        aoff[mi] = row * 128;
        asw[mi] = (row & 7) << 4;
    }
    const uint32_t axk = (q >> 1) * 16;
    uint32_t boff[4], bsw[4];
    #pragma unroll
    for (int np = 0; np < 4; np++) {
        int row = wn * 64 + np * 16 + (q >> 1) * 8 + j;
        boff[np] = row * 128;
        bsw[np] = (row & 7) << 4;
    }
    const uint32_t bxk = (q & 1) * 16;

    uint32_t c[4][8][2];
    #pragma unroll
    for (int mi = 0; mi < 4; mi++)
        #pragma unroll
        for (int ni = 0; ni < 8; ni++) { c[mi][ni][0] = 0u; c[mi][ni][1] = 0u; }

    // chunk load: cidx -> job-local jl = cidx>>4, kc = cidx&15, stage = cidx%3
    auto issue_load = [&](int cidx) {
        const int jl = cidx >> 4, kc = cidx & 15, st = cidx % 3;
        const int gj = cta + jl * NCTAS;
        const int rb = gj >> 6, jt = gj & 63;
        const __half* Asrc = g_Rh + (long)rb * BM * D + kc * BK;
        const __half* Bsrc = g_Lh + (long)jt * BN * D + kc * BK;
        const uint32_t Ab = sb + st * STAGE_BYTES;
        const uint32_t Bb = Ab + 16384;
        #pragma unroll
        for (int i = 0; i < 8; i++) cp16(Ab + swoff[i], Asrc + goff[i]);
        #pragma unroll
        for (int i = 0; i < 8; i++) cp16(Bb + swoff[i], Bsrc + goff[i]);
        asm volatile("cp.async.commit_group;");
    };

    // prologue: chunks 0,1 in flight
    issue_load(0);
    issue_load(1);

    for (int cidx = 0; cidx < totc; ++cidx) {
        asm volatile("cp.async.wait_group 1;");
        __syncthreads();
        if (cidx + 2 < totc) issue_load(cidx + 2);

        const int st = cidx % 3;
        const uint32_t Ast = sb + st * STAGE_BYTES;
        const uint32_t Bst = Ast + 16384;
        #pragma unroll
        for (int kk = 0; kk < 4; ++kk) {
            const uint32_t kx = kk * 32;
            uint32_t a[4][4], b[4][4];
            #pragma unroll
            for (int mi = 0; mi < 4; mi++)
                ldsm4(a[mi], Ast + aoff[mi] + ((kx + axk) ^ asw[mi]));
            #pragma unroll
            for (int np = 0; np < 4; np++)
                ldsm4(b[np], Bst + boff[np] + ((kx + bxk) ^ bsw[np]));
            #pragma unroll
            for (int mi = 0; mi < 4; mi++)
                #pragma unroll
                for (int ni = 0; ni < 8; ni++) {
                    const int np = ni >> 1, lo = ni & 1;
                    mma16816h(c[mi][ni], a[mi], b[np][lo * 2], b[np][lo * 2 + 1]);
                }
        }

        if ((cidx & 15) == 15) {
            // ---- per-job epilogue: direct (m, s) of this 128-col tile ----
            const int gj = cta + (cidx >> 4) * NCTAS;
            const long pbase = (long)gj * 256 + wn * 128;
            #pragma unroll
            for (int mi = 0; mi < 4; mi++)
                #pragma unroll
                for (int h = 0; h < 2; h++) {
                    float2 v[8];
                    #pragma unroll
                    for (int ni = 0; ni < 8; ni++)
                        v[ni] = __half22float2(*(__half2*)&c[mi][ni][h]);
                    float mx = fmaxf(v[0].x, v[0].y);
                    #pragma unroll
                    for (int ni = 1; ni < 8; ni++)
                        mx = fmaxf(mx, fmaxf(v[ni].x, v[ni].y));
                    mx = fmaxf(mx, __shfl_xor_sync(0xffffffffu, mx, 1));
                    mx = fmaxf(mx, __shfl_xor_sync(0xffffffffu, mx, 2));
                    const float nb = -mx * LOG2E;
                    float s0 = 0.f, s1 = 0.f;
                    #pragma unroll
                    for (int ni = 0; ni < 8; ni++) {
                        s0 += ex2f(fmaf(v[ni].x, LOG2E, nb));
                        s1 += ex2f(fmaf(v[ni].y, LOG2E, nb));
                    }
                    float sum = s0 + s1;
                    sum += __shfl_xor_sync(0xffffffffu, sum, 1);
                    sum += __shfl_xor_sync(0xffffffffu, sum, 2);
                    if ((lane & 3) == 0) {
                        int row = wm * 64 + mi * 16 + h * 8 + (lane >> 2);
                        g_pm[pbase + row] = mx;
                        g_ps[pbase + row] = sum;
                    }
                }
            #pragma unroll
            for (int mi = 0; mi < 4; mi++)
                #pragma unroll
                for (int ni = 0; ni < 8; ni++) { c[mi][ni][0] = 0u; c[mi][ni][1] = 0u; }
        }
    }
}

// ---------------------------------------------------------------------------
// Kernel 4a: per-row merge of 128 partials -> lse - diag (parallel, coalesced)
// ---------------------------------------------------------------------------
__global__ void finalize1_kernel() {
    const int i = blockIdx.x * blockDim.x + threadIdx.x;   // row 0..8191
    const int rb = i >> 7, r = i & 127;
    const long base = (long)(rb * 64) * 256 + r;           // jobs rb*64 .. rb*64+63
    float mm = -INFINITY;
    #pragma unroll 4
    for (int p = 0; p < 128; p++)                          // p = jt*2 + wn
        mm = fmaxf(mm, g_pm[base + (p >> 1) * 256 + (p & 1) * 128]);
    float ss = 0.f;
    #pragma unroll 4
    for (int p = 0; p < 128; p++) {
        long o = base + (p >> 1) * 256 + (p & 1) * 128;
        ss += g_ps[o] * __expf(g_pm[o] - mm);
    }
    g_row[i] = mm + logf(ss) - g_diag[i];
}

// ---------------------------------------------------------------------------
// Kernel 4b: sum 8192 per-row values -> scalar
// ---------------------------------------------------------------------------
__global__ void finalize2_kernel(float* __restrict__ out) {
    __shared__ double red[256];
    double acc = 0.0;
    for (int i = threadIdx.x; i < N; i += 256) acc += (double)g_row[i];
    red[threadIdx.x] = acc;
    __syncthreads();
    for (int s = 128; s > 0; s >>= 1) {
        if (threadIdx.x < s) red[threadIdx.x] += red[threadIdx.x + s];
        __syncthreads();
    }
    if (threadIdx.x == 0) out[0] = (float)(red[0] / (double)N);
}

// ---------------------------------------------------------------------------
extern "C" void kernel_launch(void* const* d_in, const int* in_sizes, int n_in,
                              void* d_out, int out_size) {
    const float* R = (const float*)d_in[0];   // rpr_r [N, D]
    const float* L = (const float*)d_in[1];   // rpr_l [N, D]
    float* out = (float*)d_out;

    cudaFuncSetAttribute(lse_kernel, cudaFuncAttributeMaxDynamicSharedMemorySize, SMEM_TOTAL);

    convert_kernel<<<N, 256>>>(R, L);
    pad_kernel<<<1, 32>>>();
    pad_kernel<<<1, 32>>>();
    lse_kernel<<<NCTAS, THREADS, SMEM_TOTAL>>>();
    finalize1_kernel<<<N / 128, 128>>>();
    finalize2_kernel<<<1, 256>>>(out);
}